// round 3
// baseline (speedup 1.0000x reference)
#include <cuda_runtime.h>

#define QSCALE 0.17677669529663687f   // 32^-0.5

typedef unsigned long long u64;

// ---------------------------------------------------------------------------
// Scratch (static device arrays; no allocation allowed)
// ---------------------------------------------------------------------------
__device__ __align__(16) float g_wt [1152 * 1024];        // K-major weights [k][co]
__device__ __align__(16) float g_q  [32 * 1024 * 32];     // [bh][pos][d] (scaled)
__device__ __align__(16) float g_k  [32 * 1024 * 32];
__device__ __align__(16) float g_v  [32 * 1024 * 32];
__device__ __align__(16) float g_rx [32 * 1024 * 32];     // [bh][i][jc]
__device__ __align__(16) float g_ry [32 * 1024 * 32];     // [bh][i][jr]
__device__ __align__(16) float g_att[4 * 256 * 1024];     // scrambled-channel att

// ---------------------------------------------------------------------------
// f32x2 packed helpers
// ---------------------------------------------------------------------------
__device__ __forceinline__ u64 pk2(float lo, float hi) {
    u64 r; asm("mov.b64 %0,{%1,%2};" : "=l"(r) : "f"(lo), "f"(hi)); return r;
}
__device__ __forceinline__ void upk2(float& lo, float& hi, u64 v) {
    asm("mov.b64 {%0,%1},%2;" : "=f"(lo), "=f"(hi) : "l"(v));
}
__device__ __forceinline__ void ffma2(u64& d, u64 a, u64 b) {
    asm("fma.rn.f32x2 %0,%1,%2,%0;" : "+l"(d) : "l"(a), "l"(b));
}
__device__ __forceinline__ u64 fmul2(u64 a, u64 b) {
    u64 d; asm("mul.rn.f32x2 %0,%1,%2;" : "=l"(d) : "l"(a), "l"(b)); return d;
}

// ---------------------------------------------------------------------------
// K0: tiled coalesced transpose -> K-major [k][co]
//     co 0..255 = conv_w, 256..1023 = qkv_w. Grid (36, 32), 256 threads.
// ---------------------------------------------------------------------------
__global__ __launch_bounds__(256) void k_wt(const float* __restrict__ cw,
                                            const float* __restrict__ qw) {
    __shared__ float T[32][33];
    const int tx = threadIdx.x & 31, ty = threadIdx.x >> 5;
    const int k0 = blockIdx.x * 32, c0 = blockIdx.y * 32;
#pragma unroll
    for (int r = 0; r < 4; r++) {
        int co = c0 + ty + r * 8;
        const float* src = (co < 256) ? cw + (size_t)co * 1152
                                      : qw + (size_t)(co - 256) * 1152;
        T[ty + r * 8][tx] = src[k0 + tx];
    }
    __syncthreads();
#pragma unroll
    for (int r = 0; r < 4; r++) {
        int k = k0 + ty + r * 8;
        g_wt[(size_t)k * 1024 + c0 + tx] = T[tx][ty + r * 8];
    }
}

// ---------------------------------------------------------------------------
// K1: fused 3x3 conv. Block: 128 co x 64 pos (2 rows). 256 thr, tile 8co x 4pos.
// ---------------------------------------------------------------------------
__global__ __launch_bounds__(256) void k_conv(const float* __restrict__ x,
                                              const float* __restrict__ cb,
                                              const float* __restrict__ qb,
                                              float* __restrict__ out) {
    __shared__ __align__(16) float Ws[72 * 128];   // [ci_l*9+tap][co_l]
    __shared__ float Xs[8 * 4 * 37];               // [ci_l][row][col(-1..35)]

    const int tid = threadIdx.x;
    const int b   = blockIdx.x >> 4;
    const int y0  = (blockIdx.x & 15) << 1;
    const int co_base = blockIdx.y << 7;
    const int cg = tid >> 4, pg = tid & 15;
    const int ly = pg >> 3, lx0 = (pg & 7) << 2;
    const int co0 = co_base + cg * 8;

    u64 acc[4][4];
#pragma unroll
    for (int a = 0; a < 4; a++)
#pragma unroll
        for (int c = 0; c < 4; c++) acc[a][c] = 0ULL;

    for (int ch = 0; ch < 16; ch++) {
        const int ci0 = ch << 3;
        __syncthreads();
        for (int t = tid; t < 72 * 32; t += 256) {
            int row = t >> 5, f = t & 31;
            *(float4*)&Ws[row * 128 + f * 4] =
                *(const float4*)&g_wt[(size_t)(ci0 * 9 + row) * 1024 + co_base + f * 4];
        }
        for (int t = tid; t < 1184; t += 256) {
            int ci  = t / 148;
            int rem = t - ci * 148;
            int rr  = rem / 37;
            int c   = rem - rr * 37;
            int gy = y0 - 1 + rr;
            int gx = c - 1;
            float v = 0.f;
            if (gy >= 0 && gy < 32 && (unsigned)gx < 32u)
                v = x[(size_t)((b * 128 + ci0 + ci) * 32 + gy) * 32 + gx];
            Xs[t] = v;
        }
        __syncthreads();
#pragma unroll
        for (int ci = 0; ci < 8; ci++) {
#pragma unroll
            for (int ky = 0; ky < 3; ky++) {
                const float* xp = Xs + ci * 148 + (ly + ky) * 37 + lx0;
                u64 xb[6];
#pragma unroll
                for (int t = 0; t < 6; t++) { float xv = xp[t]; xb[t] = pk2(xv, xv); }
#pragma unroll
                for (int kx = 0; kx < 3; kx++) {
                    const ulonglong2* wp =
                        (const ulonglong2*)(Ws + (ci * 9 + ky * 3 + kx) * 128 + cg * 8);
                    ulonglong2 wA = wp[0], wB = wp[1];
#pragma unroll
                    for (int c = 0; c < 4; c++) {
                        ffma2(acc[0][c], wA.x, xb[kx + c]);
                        ffma2(acc[1][c], wA.y, xb[kx + c]);
                        ffma2(acc[2][c], wB.x, xb[kx + c]);
                        ffma2(acc[3][c], wB.y, xb[kx + c]);
                    }
                }
            }
        }
    }

    float bias[8];
    const float* bsrc = (co0 < 256) ? (cb + co0) : (qb + co0 - 256);
#pragma unroll
    for (int t = 0; t < 8; t++) bias[t] = bsrc[t];

    float v[8][4];
#pragma unroll
    for (int a = 0; a < 4; a++)
#pragma unroll
        for (int c = 0; c < 4; c++) {
            float lo, hi; upk2(lo, hi, acc[a][c]);
            v[2 * a][c]     = lo + bias[2 * a];
            v[2 * a + 1][c] = hi + bias[2 * a + 1];
        }

    const int base_pos = (y0 + ly) * 32 + lx0;
    if (co0 < 256) {
#pragma unroll
        for (int cc = 0; cc < 8; cc++)
            *(float4*)&out[(size_t)(b * 512 + co0 + cc) * 1024 + base_pos] =
                make_float4(v[cc][0], v[cc][1], v[cc][2], v[cc][3]);
    } else {
        int qc0 = co0 - 256;
        int seg = qc0 >> 8;              // 0=q 1=k 2=v
        int c8  = qc0 & 255;
        int h = c8 >> 5, d0 = c8 & 31;
        float* dstb = (seg == 0 ? g_q : (seg == 1 ? g_k : g_v))
                      + (size_t)((b * 8 + h) * 1024) * 32 + d0;
        float scale = (seg == 0) ? QSCALE : 1.f;
#pragma unroll
        for (int c = 0; c < 4; c++) {
            int pos = base_pos + c;
            *(float4*)(dstb + (size_t)pos * 32) =
                make_float4(v[0][c] * scale, v[1][c] * scale, v[2][c] * scale, v[3][c] * scale);
            *(float4*)(dstb + (size_t)pos * 32 + 4) =
                make_float4(v[4][c] * scale, v[5][c] * scale, v[6][c] * scale, v[7][c] * scale);
        }
    }
}

// ---------------------------------------------------------------------------
// K2: rel-logit tables.
//   RX[bh][i][jc] = q_i . kr_x[jc - (i&31) + 31]
//   RY[bh][i][jr] = q_{(i&31)*32+(i>>5)} . kr_y[jr - (i&31) + 31]
// ---------------------------------------------------------------------------
__global__ __launch_bounds__(256) void k_rel(const float* __restrict__ krx,
                                             const float* __restrict__ kry) {
    __shared__ float KX[63 * 33], KY[63 * 33], QR[32 * 32], QT[32 * 32];
    const int bh = blockIdx.x, qg = blockIdx.y, tid = threadIdx.x;

    for (int t = tid; t < 63 * 32; t += 256) {
        int m = t >> 5, d = t & 31;
        KX[m * 33 + d] = krx[t];
        KY[m * 33 + d] = kry[t];
    }
    for (int t = tid; t < 1024; t += 256) {
        int il = t >> 5, d = t & 31;
        QR[t] = g_q[(size_t)(bh * 1024 + qg * 32 + il) * 32 + d];
        QT[t] = g_q[(size_t)(bh * 1024 + il * 32 + qg) * 32 + d];
    }
    __syncthreads();

    const int wid = tid >> 5, j = tid & 31;
#pragma unroll
    for (int r = 0; r < 4; r++) {
        int il = r * 8 + wid;
        int m = j - il + 31;
        float ax = 0.f, ay = 0.f;
#pragma unroll
        for (int d = 0; d < 32; d++) {
            ax += QR[il * 32 + d] * KX[m * 33 + d];
            ay += QT[il * 32 + d] * KY[m * 33 + d];
        }
        int i = qg * 32 + il;
        g_rx[(size_t)(bh * 1024 + i) * 32 + j] = ax;
        g_ry[(size_t)(bh * 1024 + i) * 32 + j] = ay;
    }
}

// ---------------------------------------------------------------------------
// K3: flash attention, split-K(keys) x2. Block = 128 thr = 2 groups x 64 queries.
// Group g handles key tiles [g*16, g*16+16); states merged via smem at the end.
// ---------------------------------------------------------------------------
__global__ __launch_bounds__(128) void k_attn() {
    __shared__ __align__(16) float Ks[2][32 * 32];
    __shared__ __align__(16) float Vs[2][32 * 32];
    __shared__ float RXs[64 * 33], RYs[64 * 33];
    __shared__ float Ms[64], Ls[64];
    __shared__ __align__(16) float AVs[64 * 32];

    const int bh = blockIdx.x, qt = blockIdx.y, tid = threadIdx.x;
    const int q  = tid & 63;
    const int g  = tid >> 6;
    const int i  = qt * 64 + q;

    u64 q2[16];
    {
        const ulonglong2* qp = (const ulonglong2*)(g_q + (size_t)(bh * 1024 + i) * 32);
#pragma unroll
        for (int t = 0; t < 8; t++) { ulonglong2 vv = qp[t]; q2[2 * t] = vv.x; q2[2 * t + 1] = vv.y; }
    }
    for (int t = tid; t < 2048; t += 128) {
        int ql = t >> 5, j = t & 31;
        RXs[ql * 33 + j] = g_rx[(size_t)(bh * 1024 + qt * 64 + ql) * 32 + j];
        RYs[ql * 33 + j] = g_ry[(size_t)(bh * 1024 + qt * 64 + ql) * 32 + j];
    }

    const u64 ONE2 = pk2(1.f, 1.f);
    float m = -1e30f, l = 0.f;
    u64 av[16];
#pragma unroll
    for (int t = 0; t < 16; t++) av[t] = 0ULL;

    for (int jt = 0; jt < 16; jt++) {
        const int jtg = g * 16 + jt;
        __syncthreads();
        for (int t = q; t < 512; t += 64) {
            int sel = t >> 8, r = (t & 255) >> 3, f = t & 7;
            const float* src = (sel ? g_v : g_k)
                               + (size_t)(bh * 1024 + jtg * 32 + r) * 32 + f * 4;
            *(float4*)((sel ? Vs[g] : Ks[g]) + r * 32 + f * 4) = *(const float4*)src;
        }
        __syncthreads();

        const float ry = RYs[q * 33 + jtg];
        float s[32];
#pragma unroll
        for (int j = 0; j < 32; j++) {
            u64 a0 = 0ULL, a1 = 0ULL;
            const ulonglong2* kp = (const ulonglong2*)(Ks[g] + j * 32);
#pragma unroll
            for (int t2 = 0; t2 < 4; t2++) {
                ulonglong2 kA = kp[2 * t2], kB = kp[2 * t2 + 1];
                ffma2(a0, q2[4 * t2 + 0], kA.x);
                ffma2(a1, q2[4 * t2 + 1], kA.y);
                ffma2(a0, q2[4 * t2 + 2], kB.x);
                ffma2(a1, q2[4 * t2 + 3], kB.y);
            }
            ffma2(a0, ONE2, a1);
            float lo, hi; upk2(lo, hi, a0);
            s[j] = lo + hi + RXs[q * 33 + j] + ry;
        }

        float mt = fmaxf(s[0], s[1]);
#pragma unroll
        for (int j = 2; j < 32; j += 2) mt = fmaxf(mt, fmaxf(s[j], s[j + 1]));
        float mnew = fmaxf(m, mt);
        float sc = __expf(m - mnew);
        l *= sc;
        u64 sc2 = pk2(sc, sc);
#pragma unroll
        for (int t2 = 0; t2 < 16; t2++) av[t2] = fmul2(av[t2], sc2);

#pragma unroll
        for (int j = 0; j < 32; j++) {
            float p = __expf(s[j] - mnew);
            l += p;
            u64 p2 = pk2(p, p);
            const ulonglong2* vp = (const ulonglong2*)(Vs[g] + j * 32);
#pragma unroll
            for (int t2 = 0; t2 < 8; t2++) {
                ulonglong2 vv = vp[t2];
                ffma2(av[2 * t2],     p2, vv.x);
                ffma2(av[2 * t2 + 1], p2, vv.y);
            }
        }
        m = mnew;
    }

    // merge the two key-half states, then write scrambled layout:
    // channel = h*32 + (i>>5), pos = (i&31)*32 + d
    __syncthreads();
    if (g == 1) {
        Ms[q] = m; Ls[q] = l;
        float* dst = AVs + q * 32;
#pragma unroll
        for (int t = 0; t < 8; t++) {
            float a0, a1, a2, a3;
            upk2(a0, a1, av[2 * t]); upk2(a2, a3, av[2 * t + 1]);
            ((float4*)dst)[t] = make_float4(a0, a1, a2, a3);
        }
    }
    __syncthreads();
    if (g == 0) {
        float m1 = Ms[q], l1 = Ls[q];
        float mM = fmaxf(m, m1);
        float s0 = __expf(m - mM), s1 = __expf(m1 - mM);
        float inv = 1.0f / (l * s0 + l1 * s1);
        int b = bh >> 3, h = bh & 7;
        float* dst = g_att + (size_t)(b * 256 + h * 32 + (i >> 5)) * 1024 + (i & 31) * 32;
        const float4* pav = (const float4*)(AVs + q * 32);
#pragma unroll
        for (int t = 0; t < 8; t++) {
            float a0, a1, a2, a3;
            upk2(a0, a1, av[2 * t]); upk2(a2, a3, av[2 * t + 1]);
            float4 pv = pav[t];
            ((float4*)dst)[t] = make_float4((a0 * s0 + pv.x * s1) * inv,
                                            (a1 * s0 + pv.y * s1) * inv,
                                            (a2 * s0 + pv.z * s1) * inv,
                                            (a3 * s0 + pv.w * s1) * inv);
        }
    }
}

// ---------------------------------------------------------------------------
// K4: 1x1 projection of attention output -> output channels [256,512)
// ---------------------------------------------------------------------------
__global__ __launch_bounds__(256) void k_proj(const float* __restrict__ aw,
                                              const float* __restrict__ ab,
                                              float* __restrict__ out) {
    __shared__ float As[64 * 68];
    __shared__ float Wt[64 * 65];
    const int bx = blockIdx.x;
    const int b = bx >> 4;
    const int pos0 = (bx & 15) * 64;
    const int co0 = blockIdx.y * 64;
    const int tid = threadIdx.x;
    const int cg = tid >> 4, pg = tid & 15;
    const int col0 = cg * 4, pl0 = pg * 4;

    float acc[4][4] = {};

    for (int cc = 0; cc < 4; cc++) {
        const int ci0 = cc * 64;
        __syncthreads();
        for (int t = tid; t < 1024; t += 256) {
            int rl = t >> 4, f = t & 15;
            *(float4*)&As[rl * 68 + f * 4] =
                *(const float4*)&g_att[(size_t)(b * 256 + ci0 + rl) * 1024 + pos0 + f * 4];
            float4 wv = *(const float4*)&aw[(co0 + rl) * 256 + ci0 + f * 4];
            Wt[(f * 4 + 0) * 65 + rl] = wv.x;
            Wt[(f * 4 + 1) * 65 + rl] = wv.y;
            Wt[(f * 4 + 2) * 65 + rl] = wv.z;
            Wt[(f * 4 + 3) * 65 + rl] = wv.w;
        }
        __syncthreads();
#pragma unroll 8
        for (int k = 0; k < 64; k++) {
            float wv[4], avv[4];
#pragma unroll
            for (int t = 0; t < 4; t++) wv[t]  = Wt[k * 65 + col0 + t];
#pragma unroll
            for (int t = 0; t < 4; t++) avv[t] = As[k * 68 + pl0 + t];
#pragma unroll
            for (int a = 0; a < 4; a++)
#pragma unroll
                for (int p = 0; p < 4; p++) acc[a][p] += wv[a] * avv[p];
        }
    }

#pragma unroll
    for (int a = 0; a < 4; a++) {
        int co = co0 + col0 + a;
        float bb = ab[co];
        *(float4*)&out[(size_t)(b * 512 + 256 + co) * 1024 + pos0 + pl0] =
            make_float4(acc[a][0] + bb, acc[a][1] + bb, acc[a][2] + bb, acc[a][3] + bb);
    }
}

// ---------------------------------------------------------------------------
extern "C" void kernel_launch(void* const* d_in, const int* in_sizes, int n_in,
                              void* d_out, int out_size) {
    const float* x   = (const float*)d_in[0];
    const float* cw  = (const float*)d_in[1];
    const float* cb  = (const float*)d_in[2];
    const float* qw  = (const float*)d_in[3];
    const float* qb  = (const float*)d_in[4];
    const float* aw  = (const float*)d_in[5];
    const float* ab  = (const float*)d_in[6];
    const float* krx = (const float*)d_in[7];
    const float* kry = (const float*)d_in[8];
    float* out = (float*)d_out;

    k_wt  <<<dim3(36, 32), 256>>>(cw, qw);
    k_conv<<<dim3(64, 8), 256>>>(x, cb, qb, out);
    k_rel <<<dim3(32, 32), 256>>>(krx, kry);
    k_attn<<<dim3(32, 16), 128>>>();
    k_proj<<<dim3(64, 4), 256>>>(aw, ab, out);
}

// round 4
// speedup vs baseline: 1.1034x; 1.1034x over previous
#include <cuda_runtime.h>

#define QSCALE 0.17677669529663687f   // 32^-0.5

typedef unsigned long long u64;
typedef unsigned int u32;

// ---------------------------------------------------------------------------
// Scratch (static device arrays; no allocation allowed)
// ---------------------------------------------------------------------------
__device__ __align__(16) float g_wt [1152 * 1024];        // K-major weights [k][co]
__device__ __align__(16) float g_q  [32 * 1024 * 32];     // [bh][pos][d] (scaled)
__device__ __align__(16) float g_k  [32 * 1024 * 32];
__device__ __align__(16) float g_v  [32 * 1024 * 32];
__device__ __align__(16) float g_rx [32 * 1024 * 32];     // [bh][i][jc]
__device__ __align__(16) float g_ry [32 * 1024 * 32];     // [bh][i][jr]
__device__ __align__(16) float g_att[4 * 256 * 1024];     // scrambled-channel att

// ---------------------------------------------------------------------------
// f32x2 packed helpers (conv path)
// ---------------------------------------------------------------------------
__device__ __forceinline__ u64 pk2(float lo, float hi) {
    u64 r; asm("mov.b64 %0,{%1,%2};" : "=l"(r) : "f"(lo), "f"(hi)); return r;
}
__device__ __forceinline__ void upk2(float& lo, float& hi, u64 v) {
    asm("mov.b64 {%0,%1},%2;" : "=f"(lo), "=f"(hi) : "l"(v));
}
__device__ __forceinline__ void ffma2(u64& d, u64 a, u64 b) {
    asm("fma.rn.f32x2 %0,%1,%2,%0;" : "+l"(d) : "l"(a), "l"(b));
}

// ---------------------------------------------------------------------------
// tf32 helpers (attention path)
// ---------------------------------------------------------------------------
__device__ __forceinline__ u32 tf32_of(float f) {
    u32 r; asm("cvt.rna.tf32.f32 %0,%1;" : "=r"(r) : "f"(f)); return r;
}
__device__ __forceinline__ void tf32_split(float v, u32& h, u32& l) {
    h = tf32_of(v);
    l = tf32_of(v - __uint_as_float(h));
}
#define MMA_TF32(d0,d1,d2,d3,a0,a1,a2,a3,b0,b1)                               \
    asm("mma.sync.aligned.m16n8k8.row.col.f32.tf32.tf32.f32 "                  \
        "{%0,%1,%2,%3},{%4,%5,%6,%7},{%8,%9},{%0,%1,%2,%3};"                   \
        : "+f"(d0), "+f"(d1), "+f"(d2), "+f"(d3)                               \
        : "r"(a0), "r"(a1), "r"(a2), "r"(a3), "r"(b0), "r"(b1))

// ---------------------------------------------------------------------------
// K0: tiled coalesced transpose -> K-major [k][co]
// ---------------------------------------------------------------------------
__global__ __launch_bounds__(256) void k_wt(const float* __restrict__ cw,
                                            const float* __restrict__ qw) {
    __shared__ float T[32][33];
    const int tx = threadIdx.x & 31, ty = threadIdx.x >> 5;
    const int k0 = blockIdx.x * 32, c0 = blockIdx.y * 32;
#pragma unroll
    for (int r = 0; r < 4; r++) {
        int co = c0 + ty + r * 8;
        const float* src = (co < 256) ? cw + (size_t)co * 1152
                                      : qw + (size_t)(co - 256) * 1152;
        T[ty + r * 8][tx] = src[k0 + tx];
    }
    __syncthreads();
#pragma unroll
    for (int r = 0; r < 4; r++) {
        int k = k0 + ty + r * 8;
        g_wt[(size_t)k * 1024 + c0 + tx] = T[tx][ty + r * 8];
    }
}

// ---------------------------------------------------------------------------
// K1: fused 3x3 conv. Block: 128 co x 64 pos (2 rows). 256 thr, tile 8co x 4pos.
// ---------------------------------------------------------------------------
__global__ __launch_bounds__(256) void k_conv(const float* __restrict__ x,
                                              const float* __restrict__ cb,
                                              const float* __restrict__ qb,
                                              float* __restrict__ out) {
    __shared__ __align__(16) float Ws[72 * 128];
    __shared__ float Xs[8 * 4 * 37];

    const int tid = threadIdx.x;
    const int b   = blockIdx.x >> 4;
    const int y0  = (blockIdx.x & 15) << 1;
    const int co_base = blockIdx.y << 7;
    const int cg = tid >> 4, pg = tid & 15;
    const int ly = pg >> 3, lx0 = (pg & 7) << 2;
    const int co0 = co_base + cg * 8;

    u64 acc[4][4];
#pragma unroll
    for (int a = 0; a < 4; a++)
#pragma unroll
        for (int c = 0; c < 4; c++) acc[a][c] = 0ULL;

    for (int ch = 0; ch < 16; ch++) {
        const int ci0 = ch << 3;
        __syncthreads();
        for (int t = tid; t < 72 * 32; t += 256) {
            int row = t >> 5, f = t & 31;
            *(float4*)&Ws[row * 128 + f * 4] =
                *(const float4*)&g_wt[(size_t)(ci0 * 9 + row) * 1024 + co_base + f * 4];
        }
        for (int t = tid; t < 1184; t += 256) {
            int ci  = t / 148;
            int rem = t - ci * 148;
            int rr  = rem / 37;
            int c   = rem - rr * 37;
            int gy = y0 - 1 + rr;
            int gx = c - 1;
            float v = 0.f;
            if (gy >= 0 && gy < 32 && (unsigned)gx < 32u)
                v = x[(size_t)((b * 128 + ci0 + ci) * 32 + gy) * 32 + gx];
            Xs[t] = v;
        }
        __syncthreads();
#pragma unroll
        for (int ci = 0; ci < 8; ci++) {
#pragma unroll
            for (int ky = 0; ky < 3; ky++) {
                const float* xp = Xs + ci * 148 + (ly + ky) * 37 + lx0;
                u64 xb[6];
#pragma unroll
                for (int t = 0; t < 6; t++) { float xv = xp[t]; xb[t] = pk2(xv, xv); }
#pragma unroll
                for (int kx = 0; kx < 3; kx++) {
                    const ulonglong2* wp =
                        (const ulonglong2*)(Ws + (ci * 9 + ky * 3 + kx) * 128 + cg * 8);
                    ulonglong2 wA = wp[0], wB = wp[1];
#pragma unroll
                    for (int c = 0; c < 4; c++) {
                        ffma2(acc[0][c], wA.x, xb[kx + c]);
                        ffma2(acc[1][c], wA.y, xb[kx + c]);
                        ffma2(acc[2][c], wB.x, xb[kx + c]);
                        ffma2(acc[3][c], wB.y, xb[kx + c]);
                    }
                }
            }
        }
    }

    float bias[8];
    const float* bsrc = (co0 < 256) ? (cb + co0) : (qb + co0 - 256);
#pragma unroll
    for (int t = 0; t < 8; t++) bias[t] = bsrc[t];

    float v[8][4];
#pragma unroll
    for (int a = 0; a < 4; a++)
#pragma unroll
        for (int c = 0; c < 4; c++) {
            float lo, hi; upk2(lo, hi, acc[a][c]);
            v[2 * a][c]     = lo + bias[2 * a];
            v[2 * a + 1][c] = hi + bias[2 * a + 1];
        }

    const int base_pos = (y0 + ly) * 32 + lx0;
    if (co0 < 256) {
#pragma unroll
        for (int cc = 0; cc < 8; cc++)
            *(float4*)&out[(size_t)(b * 512 + co0 + cc) * 1024 + base_pos] =
                make_float4(v[cc][0], v[cc][1], v[cc][2], v[cc][3]);
    } else {
        int qc0 = co0 - 256;
        int seg = qc0 >> 8;              // 0=q 1=k 2=v
        int c8  = qc0 & 255;
        int h = c8 >> 5, d0 = c8 & 31;
        float* dstb = (seg == 0 ? g_q : (seg == 1 ? g_k : g_v))
                      + (size_t)((b * 8 + h) * 1024) * 32 + d0;
        float scale = (seg == 0) ? QSCALE : 1.f;
#pragma unroll
        for (int c = 0; c < 4; c++) {
            int pos = base_pos + c;
            *(float4*)(dstb + (size_t)pos * 32) =
                make_float4(v[0][c] * scale, v[1][c] * scale, v[2][c] * scale, v[3][c] * scale);
            *(float4*)(dstb + (size_t)pos * 32 + 4) =
                make_float4(v[4][c] * scale, v[5][c] * scale, v[6][c] * scale, v[7][c] * scale);
        }
    }
}

// ---------------------------------------------------------------------------
// K2: rel-logit tables.
//   RX[bh][i][jc] = q_i . kr_x[jc - (i&31) + 31]
//   RY[bh][i][jr] = q_{(i&31)*32+(i>>5)} . kr_y[jr - (i&31) + 31]
// ---------------------------------------------------------------------------
__global__ __launch_bounds__(256) void k_rel(const float* __restrict__ krx,
                                             const float* __restrict__ kry) {
    __shared__ float KX[63 * 33], KY[63 * 33], QR[32 * 32], QT[32 * 32];
    const int bh = blockIdx.x, qg = blockIdx.y, tid = threadIdx.x;

    for (int t = tid; t < 63 * 32; t += 256) {
        int m = t >> 5, d = t & 31;
        KX[m * 33 + d] = krx[t];
        KY[m * 33 + d] = kry[t];
    }
    for (int t = tid; t < 1024; t += 256) {
        int il = t >> 5, d = t & 31;
        QR[t] = g_q[(size_t)(bh * 1024 + qg * 32 + il) * 32 + d];
        QT[t] = g_q[(size_t)(bh * 1024 + il * 32 + qg) * 32 + d];
    }
    __syncthreads();

    const int wid = tid >> 5, j = tid & 31;
#pragma unroll
    for (int r = 0; r < 4; r++) {
        int il = r * 8 + wid;
        int m = j - il + 31;
        float ax = 0.f, ay = 0.f;
#pragma unroll
        for (int d = 0; d < 32; d++) {
            ax += QR[il * 32 + d] * KX[m * 33 + d];
            ay += QT[il * 32 + d] * KY[m * 33 + d];
        }
        int i = qg * 32 + il;
        g_rx[(size_t)(bh * 1024 + i) * 32 + j] = ax;
        g_ry[(size_t)(bh * 1024 + i) * 32 + j] = ay;
    }
}

// ---------------------------------------------------------------------------
// K3: tensor-core attention. Block = (bh, 32-query tile), 256 thr (8 warps).
// Full score row (32 x 1024) kept in smem; QK^T via split-tf32 mma.sync
// (fp32-grade), softmax in-block, PV via plain tf32 mma.sync.
// Warp w owns keys [w*128, (w+1)*128).
// ---------------------------------------------------------------------------
#define S_STRIDE 1032
#define SM_S   0
#define SM_RX  (32 * S_STRIDE)                 // 33024 floats
#define SM_RY  (SM_RX + 1024)
#define SM_OP  (SM_RY + 1024)                  // [8][32][36]
#define SM_INV (SM_OP + 8 * 32 * 36)
#define SM_FLOATS (SM_INV + 32)                // 44320 floats = 177280 B

__global__ __launch_bounds__(256) void k_attn() {
    extern __shared__ float sm[];
    float* S   = sm + SM_S;
    float* RX  = sm + SM_RX;
    float* RY  = sm + SM_RY;
    float* OP  = sm + SM_OP;
    float* INV = sm + SM_INV;

    const int bh = blockIdx.x, qt = blockIdx.y;
    const int tid = threadIdx.x, w = tid >> 5, lane = tid & 31;
    const int gid = lane >> 2, tig = lane & 3;
    const size_t qkv_base = (size_t)bh * 1024 * 32;

    // rel tables for this block's 32 queries
    for (int t = tid; t < 1024; t += 256) {
        int r = t >> 5, c = t & 31;
        RX[t] = g_rx[(size_t)(bh * 1024 + qt * 32 + r) * 32 + c];
        RY[t] = g_ry[(size_t)(bh * 1024 + qt * 32 + r) * 32 + c];
    }

    // Q fragments (A of m16n8k8), split-tf32: [mtile][kstep][reg]
    u32 qh[2][4][4], ql[2][4][4];
#pragma unroll
    for (int mt = 0; mt < 2; mt++)
#pragma unroll
        for (int s = 0; s < 4; s++) {
            int r0 = qt * 32 + mt * 16 + gid, r1 = r0 + 8;
            int c0 = s * 8 + tig, c1 = c0 + 4;
            tf32_split(g_q[qkv_base + (size_t)r0 * 32 + c0], qh[mt][s][0], ql[mt][s][0]);
            tf32_split(g_q[qkv_base + (size_t)r1 * 32 + c0], qh[mt][s][1], ql[mt][s][1]);
            tf32_split(g_q[qkv_base + (size_t)r0 * 32 + c1], qh[mt][s][2], ql[mt][s][2]);
            tf32_split(g_q[qkv_base + (size_t)r1 * 32 + c1], qh[mt][s][3], ql[mt][s][3]);
        }
    __syncthreads();

    // ---- QK^T (+rel) into smem S ----
    const int j0 = w * 128;
    for (int nt = 0; nt < 16; nt++) {
        const int jb = j0 + nt * 8;
        u32 kh[4][2], kl[4][2];
        const float* kp = g_k + qkv_base + (size_t)(jb + gid) * 32;
#pragma unroll
        for (int s = 0; s < 4; s++) {
            tf32_split(kp[s * 8 + tig],     kh[s][0], kl[s][0]);
            tf32_split(kp[s * 8 + tig + 4], kh[s][1], kl[s][1]);
        }
#pragma unroll
        for (int mt = 0; mt < 2; mt++) {
            float d0 = 0.f, d1 = 0.f, d2 = 0.f, d3 = 0.f;
#pragma unroll
            for (int s = 0; s < 4; s++)
                MMA_TF32(d0, d1, d2, d3, qh[mt][s][0], qh[mt][s][1], qh[mt][s][2], qh[mt][s][3],
                         kh[s][0], kh[s][1]);
#pragma unroll
            for (int s = 0; s < 4; s++)
                MMA_TF32(d0, d1, d2, d3, qh[mt][s][0], qh[mt][s][1], qh[mt][s][2], qh[mt][s][3],
                         kl[s][0], kl[s][1]);
#pragma unroll
            for (int s = 0; s < 4; s++)
                MMA_TF32(d0, d1, d2, d3, ql[mt][s][0], ql[mt][s][1], ql[mt][s][2], ql[mt][s][3],
                         kh[s][0], kh[s][1]);
            const int r0 = mt * 16 + gid, r1 = r0 + 8;
            const int c0 = jb + 2 * tig, c1 = c0 + 1;
            const int jr = jb >> 5;   // same for c0,c1 (jb multiple of 8, 2*tig<8)
            S[r0 * S_STRIDE + c0] = d0 + RX[r0 * 32 + (c0 & 31)] + RY[r0 * 32 + jr];
            S[r0 * S_STRIDE + c1] = d1 + RX[r0 * 32 + (c1 & 31)] + RY[r0 * 32 + jr];
            S[r1 * S_STRIDE + c0] = d2 + RX[r1 * 32 + (c0 & 31)] + RY[r1 * 32 + jr];
            S[r1 * S_STRIDE + c1] = d3 + RX[r1 * 32 + (c1 & 31)] + RY[r1 * 32 + jr];
        }
    }
    __syncthreads();

    // ---- softmax: warp w handles rows w*4 .. w*4+3; P stored tf32-rounded ----
#pragma unroll
    for (int rr = 0; rr < 4; rr++) {
        const int row = w * 4 + rr;
        float* Sr = S + row * S_STRIDE;
        float mx = -1e30f;
#pragma unroll
        for (int i = 0; i < 8; i++) {
            float4 v = *(float4*)&Sr[i * 128 + lane * 4];
            mx = fmaxf(mx, fmaxf(fmaxf(v.x, v.y), fmaxf(v.z, v.w)));
        }
#pragma unroll
        for (int o = 16; o; o >>= 1) mx = fmaxf(mx, __shfl_xor_sync(0xffffffffu, mx, o));
        float sum = 0.f;
#pragma unroll
        for (int i = 0; i < 8; i++) {
            float4 v = *(float4*)&Sr[i * 128 + lane * 4];
            v.x = __uint_as_float(tf32_of(__expf(v.x - mx)));
            v.y = __uint_as_float(tf32_of(__expf(v.y - mx)));
            v.z = __uint_as_float(tf32_of(__expf(v.z - mx)));
            v.w = __uint_as_float(tf32_of(__expf(v.w - mx)));
            sum += (v.x + v.y) + (v.z + v.w);
            *(float4*)&Sr[i * 128 + lane * 4] = v;
        }
#pragma unroll
        for (int o = 16; o; o >>= 1) sum += __shfl_xor_sync(0xffffffffu, sum, o);
        if (lane == 0) INV[row] = 1.0f / sum;
    }
    __syncthreads();

    // ---- PV: warp w accumulates over its 128 keys; O frag 2mt x 4nt x 4 ----
    float o[2][4][4];
#pragma unroll
    for (int mt = 0; mt < 2; mt++)
#pragma unroll
        for (int nt = 0; nt < 4; nt++)
#pragma unroll
            for (int r = 0; r < 4; r++) o[mt][nt][r] = 0.f;

    for (int kt = 0; kt < 16; kt++) {
        const int jb = j0 + kt * 8;
        u32 a[2][4];
#pragma unroll
        for (int mt = 0; mt < 2; mt++) {
            int r0 = mt * 16 + gid, r1 = r0 + 8;
            a[mt][0] = __float_as_uint(S[r0 * S_STRIDE + jb + tig]);
            a[mt][1] = __float_as_uint(S[r1 * S_STRIDE + jb + tig]);
            a[mt][2] = __float_as_uint(S[r0 * S_STRIDE + jb + tig + 4]);
            a[mt][3] = __float_as_uint(S[r1 * S_STRIDE + jb + tig + 4]);
        }
        const float* vp0 = g_v + qkv_base + (size_t)(jb + tig) * 32;
        const float* vp1 = vp0 + 4 * 32;
#pragma unroll
        for (int nt = 0; nt < 4; nt++) {
            u32 b0 = tf32_of(vp0[nt * 8 + gid]);
            u32 b1 = tf32_of(vp1[nt * 8 + gid]);
            MMA_TF32(o[0][nt][0], o[0][nt][1], o[0][nt][2], o[0][nt][3],
                     a[0][0], a[0][1], a[0][2], a[0][3], b0, b1);
            MMA_TF32(o[1][nt][0], o[1][nt][1], o[1][nt][2], o[1][nt][3],
                     a[1][0], a[1][1], a[1][2], a[1][3], b0, b1);
        }
    }
    // stash warp partials
#pragma unroll
    for (int mt = 0; mt < 2; mt++)
#pragma unroll
        for (int nt = 0; nt < 4; nt++) {
            int r0 = mt * 16 + gid, r1 = r0 + 8;
            int d0 = nt * 8 + 2 * tig, d1 = d0 + 1;
            OP[(w * 32 + r0) * 36 + d0] = o[mt][nt][0];
            OP[(w * 32 + r0) * 36 + d1] = o[mt][nt][1];
            OP[(w * 32 + r1) * 36 + d0] = o[mt][nt][2];
            OP[(w * 32 + r1) * 36 + d1] = o[mt][nt][3];
        }
    __syncthreads();

    // ---- reduce 8 warp partials, normalize, write scrambled layout ----
    // i = qt*32 + r -> channel = h*32 + qt, pos = r*32 + d  (contiguous 4KB/block)
    {
        const int r  = tid >> 3;
        const int d0 = (tid & 7) * 4;
        float ax = 0.f, ay = 0.f, az = 0.f, aw = 0.f;
#pragma unroll
        for (int w2 = 0; w2 < 8; w2++) {
            float4 p = *(float4*)&OP[(w2 * 32 + r) * 36 + d0];
            ax += p.x; ay += p.y; az += p.z; aw += p.w;
        }
        const float il = INV[r];
        const int b = bh >> 3, h = bh & 7;
        float* dst = g_att + (size_t)(b * 256 + h * 32 + qt) * 1024 + r * 32 + d0;
        *(float4*)dst = make_float4(ax * il, ay * il, az * il, aw * il);
    }
}

// ---------------------------------------------------------------------------
// K4: 1x1 projection of attention output -> output channels [256,512)
// ---------------------------------------------------------------------------
__global__ __launch_bounds__(256) void k_proj(const float* __restrict__ aw,
                                              const float* __restrict__ ab,
                                              float* __restrict__ out) {
    __shared__ float As[64 * 68];
    __shared__ float Wt[64 * 65];
    const int bx = blockIdx.x;
    const int b = bx >> 4;
    const int pos0 = (bx & 15) * 64;
    const int co0 = blockIdx.y * 64;
    const int tid = threadIdx.x;
    const int cg = tid >> 4, pg = tid & 15;
    const int col0 = cg * 4, pl0 = pg * 4;

    float acc[4][4] = {};

    for (int cc = 0; cc < 4; cc++) {
        const int ci0 = cc * 64;
        __syncthreads();
        for (int t = tid; t < 1024; t += 256) {
            int rl = t >> 4, f = t & 15;
            *(float4*)&As[rl * 68 + f * 4] =
                *(const float4*)&g_att[(size_t)(b * 256 + ci0 + rl) * 1024 + pos0 + f * 4];
            float4 wv = *(const float4*)&aw[(co0 + rl) * 256 + ci0 + f * 4];
            Wt[(f * 4 + 0) * 65 + rl] = wv.x;
            Wt[(f * 4 + 1) * 65 + rl] = wv.y;
            Wt[(f * 4 + 2) * 65 + rl] = wv.z;
            Wt[(f * 4 + 3) * 65 + rl] = wv.w;
        }
        __syncthreads();
#pragma unroll 8
        for (int k = 0; k < 64; k++) {
            float wv[4], avv[4];
#pragma unroll
            for (int t = 0; t < 4; t++) wv[t]  = Wt[k * 65 + col0 + t];
#pragma unroll
            for (int t = 0; t < 4; t++) avv[t] = As[k * 68 + pl0 + t];
#pragma unroll
            for (int a = 0; a < 4; a++)
#pragma unroll
                for (int p = 0; p < 4; p++) acc[a][p] += wv[a] * avv[p];
        }
    }

#pragma unroll
    for (int a = 0; a < 4; a++) {
        int co = co0 + col0 + a;
        float bb = ab[co];
        *(float4*)&out[(size_t)(b * 512 + 256 + co) * 1024 + pos0 + pl0] =
            make_float4(acc[a][0] + bb, acc[a][1] + bb, acc[a][2] + bb, acc[a][3] + bb);
    }
}

// ---------------------------------------------------------------------------
extern "C" void kernel_launch(void* const* d_in, const int* in_sizes, int n_in,
                              void* d_out, int out_size) {
    const float* x   = (const float*)d_in[0];
    const float* cw  = (const float*)d_in[1];
    const float* cb  = (const float*)d_in[2];
    const float* qw  = (const float*)d_in[3];
    const float* qb  = (const float*)d_in[4];
    const float* aw  = (const float*)d_in[5];
    const float* ab  = (const float*)d_in[6];
    const float* krx = (const float*)d_in[7];
    const float* kry = (const float*)d_in[8];
    float* out = (float*)d_out;

    const int attn_smem = SM_FLOATS * 4;   // 177280 bytes
    cudaFuncSetAttribute(k_attn, cudaFuncAttributeMaxDynamicSharedMemorySize, attn_smem);

    k_wt  <<<dim3(36, 32), 256>>>(cw, qw);
    k_conv<<<dim3(64, 8), 256>>>(x, cb, qb, out);
    k_rel <<<dim3(32, 32), 256>>>(krx, kry);
    k_attn<<<dim3(32, 32), 256, attn_smem>>>();
    k_proj<<<dim3(64, 4), 256>>>(aw, ab, out);
}